// round 11
// baseline (speedup 1.0000x reference)
#include <cuda_runtime.h>
#include <cuda_bf16.h>
#include <math.h>
#include <stdint.h>

// ---------------------------------------------------------------------------
// Problem constants
// ---------------------------------------------------------------------------
#define BB   2
#define LL   4096
#define DD   1024
#define HH   8
#define DKH  128
#define DVH  256
#define FFND 4096
#define ROWS (BB*LL)          // 8192
#define CHK  64
#define NCHK (LL/CHK)

// ---------------------------------------------------------------------------
// Scratch (device globals -- no allocation allowed)
// ---------------------------------------------------------------------------
__device__ float g_q [ROWS*DD];
__device__ float g_k [ROWS*DD];
__device__ float g_v [ROWS*2*DD];
__device__ float g_x1[ROWS*DD];

__device__ __nv_bfloat16 g_hh[ROWS*DD],   g_hl[ROWS*DD];     // ln1 out split
__device__ __nv_bfloat16 g_oh[ROWS*2*DD], g_ol[ROWS*2*DD];   // retention out split
__device__ __nv_bfloat16 g_fh[ROWS*DD],   g_fl[ROWS*DD];     // ln2 out split
__device__ __nv_bfloat16 g_gh[ROWS*FFND], g_gl[ROWS*FFND];   // gelu out split

// transposed weight splits, [N,K] K-major
__device__ __nv_bfloat16 g_wqh[DD*DD],     g_wql[DD*DD];
__device__ __nv_bfloat16 g_wkh[DD*DD],     g_wkl[DD*DD];
__device__ __nv_bfloat16 g_wvh[2*DD*DD],   g_wvl[2*DD*DD];
__device__ __nv_bfloat16 g_woh[DD*2*DD],   g_wol[DD*2*DD];
__device__ __nv_bfloat16 g_w1h[FFND*DD],   g_w1l[FFND*DD];
__device__ __nv_bfloat16 g_w2h[DD*FFND],   g_w2l[DD*FFND];

// ---------------------------------------------------------------------------
// PTX helpers (baseline PTX only -- no sm_103a-only features)
// ---------------------------------------------------------------------------
__device__ __forceinline__ uint32_t smem_u32(const void* p){
    uint32_t a;
    asm("{ .reg .u64 t; cvta.to.shared.u64 t, %1; cvt.u32.u64 %0, t; }"
        : "=r"(a) : "l"(p));
    return a;
}
__device__ __forceinline__ void cpa16(uint32_t d, const void* s){
    asm volatile("cp.async.cg.shared.global [%0], [%1], 16;" :: "r"(d), "l"(s));
}
#define CP_COMMIT() asm volatile("cp.async.commit_group;" ::: "memory")
#define CP_WAIT0()  asm volatile("cp.async.wait_group 0;" ::: "memory")
#define CP_WAIT1()  asm volatile("cp.async.wait_group 1;" ::: "memory")

__device__ __forceinline__ void ldsm4(uint32_t& r0, uint32_t& r1,
                                      uint32_t& r2, uint32_t& r3, uint32_t a){
    asm volatile("ldmatrix.sync.aligned.m8n8.x4.shared.b16 {%0,%1,%2,%3}, [%4];"
                 : "=r"(r0), "=r"(r1), "=r"(r2), "=r"(r3) : "r"(a));
}
__device__ __forceinline__ void mma16816(float* d, const uint32_t* a, const uint32_t* b){
    asm volatile("mma.sync.aligned.m16n8k16.row.col.f32.bf16.bf16.f32 "
                 "{%0,%1,%2,%3}, {%4,%5,%6,%7}, {%8,%9}, {%0,%1,%2,%3};"
                 : "+f"(d[0]), "+f"(d[1]), "+f"(d[2]), "+f"(d[3])
                 : "r"(a[0]), "r"(a[1]), "r"(a[2]), "r"(a[3]),
                   "r"(b[0]), "r"(b[1]));
}

__device__ __forceinline__ void split_bf16(float v, __nv_bfloat16& h, __nv_bfloat16& l){
    h = __float2bfloat16(v);
    l = __float2bfloat16(v - __bfloat162float(h));
}

// ---------------------------------------------------------------------------
// LayerNorm -> bf16 hi/lo split
// ---------------------------------------------------------------------------
__global__ void ln_split(const float* __restrict__ x,
                         const float* __restrict__ w,
                         const float* __restrict__ b,
                         __nv_bfloat16* __restrict__ yh,
                         __nv_bfloat16* __restrict__ yl)
{
    const int t = threadIdx.x;
    const size_t row = blockIdx.x;
    const float4 v = ((const float4*)(x + row*DD))[t];

    float s  = v.x + v.y + v.z + v.w;
    float ss = v.x*v.x + v.y*v.y + v.z*v.z + v.w*v.w;
    #pragma unroll
    for (int o = 16; o; o >>= 1) {
        s  += __shfl_xor_sync(0xffffffffu, s,  o);
        ss += __shfl_xor_sync(0xffffffffu, ss, o);
    }
    __shared__ float sh[16];
    if ((t & 31) == 0) { sh[t >> 5] = s; sh[8 + (t >> 5)] = ss; }
    __syncthreads();
    float S = 0.f, SS = 0.f;
    #pragma unroll
    for (int i = 0; i < 8; i++) { S += sh[i]; SS += sh[8 + i]; }
    const float mu   = S * (1.f / DD);
    const float rstd = rsqrtf(SS * (1.f / DD) - mu * mu + 1e-6f);

    const float4 wv = ((const float4*)w)[t];
    const float4 bv = ((const float4*)b)[t];
    float o0 = (v.x - mu) * rstd * wv.x + bv.x;
    float o1 = (v.y - mu) * rstd * wv.y + bv.y;
    float o2 = (v.z - mu) * rstd * wv.z + bv.z;
    float o3 = (v.w - mu) * rstd * wv.w + bv.w;

    __nv_bfloat16 h0,h1,h2,h3,l0,l1,l2,l3;
    split_bf16(o0,h0,l0); split_bf16(o1,h1,l1);
    split_bf16(o2,h2,l2); split_bf16(o3,h3,l3);
    const size_t base = row*DD + 4*t;
    __nv_bfloat162 ph0; ph0.x=h0; ph0.y=h1;
    __nv_bfloat162 ph1; ph1.x=h2; ph1.y=h3;
    __nv_bfloat162 pl0; pl0.x=l0; pl0.y=l1;
    __nv_bfloat162 pl1; pl1.x=l2; pl1.y=l3;
    ((__nv_bfloat162*)(yh+base))[0] = ph0;
    ((__nv_bfloat162*)(yh+base))[1] = ph1;
    ((__nv_bfloat162*)(yl+base))[0] = pl0;
    ((__nv_bfloat162*)(yl+base))[1] = pl1;
}

// ---------------------------------------------------------------------------
// Weight transpose + split: W[K,N] fp32 -> Wh/Wl [N,K] bf16
// ---------------------------------------------------------------------------
__global__ void wsplit(const float* __restrict__ W,
                       __nv_bfloat16* __restrict__ Wh,
                       __nv_bfloat16* __restrict__ Wl, int K, int N)
{
    __shared__ float t[32][33];
    const int n0 = blockIdx.x*32, k0 = blockIdx.y*32;
    const int tx = threadIdx.x & 31, ty = threadIdx.x >> 5;   // ty 0..7
    #pragma unroll
    for (int i = 0; i < 32; i += 8)
        t[ty+i][tx] = W[(size_t)(k0+ty+i)*N + n0+tx];
    __syncthreads();
    #pragma unroll
    for (int i = 0; i < 32; i += 8) {
        const float v = t[tx][ty+i];
        __nv_bfloat16 h,l; split_bf16(v,h,l);
        const size_t o = (size_t)(n0+ty+i)*K + k0+tx;
        Wh[o] = h; Wl[o] = l;
    }
}

// ---------------------------------------------------------------------------
// mma.sync bf16 split-GEMM: C = (Ah+Al)[M,K] @ (Bh+Bl)[N,K]^T  (3 products)
// CTA 128x128, BK=32, 3-stage cp.async, 8 warps (2x4), warp tile 64x32.
// SMEM rows padded to 80B -> ldmatrix conflict-free (20r mod 32 covers all
// eight 4-bank groups).
// MODE 0: Cf = acc
// MODE 1: Cf = acc + res
// MODE 2: Cf = acc + bias + res
// MODE 3: Ch/Cl = split(gelu(acc + bias))
// ---------------------------------------------------------------------------
#define GM 128
#define GN 128
#define GK 32
#define NST 3
#define ROWB 80                    // 32 bf16 data + 16B pad
#define MATB (128*ROWB)            // 10240 B per matrix per stage
#define STGB (4*MATB)              // Ah,Al,Bh,Bl = 40960 B
#define GEMM_SMEM (NST*STGB)       // 122880 B

template<int MODE>
__global__ __launch_bounds__(256)
void gemm_tc(const __nv_bfloat16* __restrict__ Ah, const __nv_bfloat16* __restrict__ Al,
             const __nv_bfloat16* __restrict__ Bh, const __nv_bfloat16* __restrict__ Bl,
             const float* __restrict__ bias, const float* __restrict__ res,
             float* __restrict__ Cf,
             __nv_bfloat16* __restrict__ Ch, __nv_bfloat16* __restrict__ Cl,
             int M, int N, int K)
{
    extern __shared__ char smc[];
    const uint32_t sb = smem_u32(smc);
    const int tid  = threadIdx.x;
    const int wid  = tid >> 5, lane = tid & 31;
    const int m0 = blockIdx.y * GM, n0 = blockIdx.x * GN;

    const int NIT = K / GK;

    // cp.async fill of one stage: 2048 16B chunks, 8 per thread
    auto fill = [&](int kt){
        const int kb = kt * GK;
        const uint32_t tb = sb + (kt % NST) * STGB;
        #pragma unroll
        for (int i = 0; i < 8; i++) {
            const int g   = tid + i * 256;      // 0..2047
            const int m   = g >> 9;             // 0..3 : Ah,Al,Bh,Bl
            const int c   = g & 511;
            const int row = c >> 2;
            const int cb  = (c & 3) * 16;       // byte offset in k dim
            const uint32_t dst = tb + m * MATB + row * ROWB + cb;
            const int ke = kb + (cb >> 1);
            const __nv_bfloat16* sp;
            if      (m == 0) sp = Ah + (size_t)(m0 + row) * K + ke;
            else if (m == 1) sp = Al + (size_t)(m0 + row) * K + ke;
            else if (m == 2) sp = Bh + (size_t)(n0 + row) * K + ke;
            else             sp = Bl + (size_t)(n0 + row) * K + ke;
            cpa16(dst, sp);
        }
        CP_COMMIT();
    };

    fill(0);
    fill(1);

    // warp tiling
    const int wr = (wid & 1) * 64;              // warp M origin
    const int wc = (wid >> 1) * 32;             // warp N origin
    // ldmatrix per-lane row offsets (bytes, within a matrix)
    const uint32_t alr = (uint32_t)(wr + (lane & 15)) * ROWB + (uint32_t)(lane >> 4) * 16;
    const uint32_t bnr = (uint32_t)(wc + (lane & 7) + ((lane >> 4) << 3)) * ROWB
                       + (uint32_t)((lane >> 3) & 1) * 16;

    float acc[4][4][4];
    #pragma unroll
    for (int i = 0; i < 4; i++)
        #pragma unroll
        for (int j = 0; j < 4; j++)
            #pragma unroll
            for (int e = 0; e < 4; e++) acc[i][j][e] = 0.f;

    for (int kt = 0; kt < NIT; kt++) {
        if (kt == NIT - 1) CP_WAIT0(); else CP_WAIT1();
        __syncthreads();
        if (kt + 2 < NIT) fill(kt + 2);

        const uint32_t sA_h = sb + (kt % NST) * STGB;
        const uint32_t sA_l = sA_h + MATB;
        const uint32_t sB_h = sA_h + 2*MATB;
        const uint32_t sB_l = sA_h + 3*MATB;

        #pragma unroll
        for (int kk2 = 0; kk2 < 2; kk2++) {
            const uint32_t ko = kk2 * 32;       // 16 bf16 = 32 bytes
            uint32_t ah[4][4], al[4][4], bh[4][2], bl[4][2];
            #pragma unroll
            for (int mi = 0; mi < 4; mi++) {
                ldsm4(ah[mi][0], ah[mi][1], ah[mi][2], ah[mi][3],
                      sA_h + alr + mi*16*ROWB + ko);
                ldsm4(al[mi][0], al[mi][1], al[mi][2], al[mi][3],
                      sA_l + alr + mi*16*ROWB + ko);
            }
            #pragma unroll
            for (int nj2 = 0; nj2 < 2; nj2++) {
                uint32_t r0,r1,r2,r3;
                ldsm4(r0,r1,r2,r3, sB_h + bnr + nj2*16*ROWB + ko);
                bh[2*nj2][0]=r0; bh[2*nj2][1]=r1; bh[2*nj2+1][0]=r2; bh[2*nj2+1][1]=r3;
                ldsm4(r0,r1,r2,r3, sB_l + bnr + nj2*16*ROWB + ko);
                bl[2*nj2][0]=r0; bl[2*nj2][1]=r1; bl[2*nj2+1][0]=r2; bl[2*nj2+1][1]=r3;
            }
            #pragma unroll
            for (int mi = 0; mi < 4; mi++)
                #pragma unroll
                for (int nj = 0; nj < 4; nj++) {
                    mma16816(acc[mi][nj], ah[mi], bh[nj]);
                    mma16816(acc[mi][nj], ah[mi], bl[nj]);
                    mma16816(acc[mi][nj], al[mi], bh[nj]);
                }
        }
        __syncthreads();
    }

    // ------------------- epilogue -------------------
    const int cr = lane >> 2;          // 0..7
    const int cc = (lane & 3) * 2;     // 0,2,4,6
    #pragma unroll
    for (int mi = 0; mi < 4; mi++) {
        #pragma unroll
        for (int half = 0; half < 2; half++) {
            const int row = m0 + wr + 16*mi + cr + 8*half;
            #pragma unroll
            for (int nj = 0; nj < 4; nj++) {
                float d0 = acc[mi][nj][2*half + 0];
                float d1 = acc[mi][nj][2*half + 1];
                const int col = n0 + wc + 8*nj + cc;
                if (MODE == 2 || MODE == 3) {
                    d0 += bias[col]; d1 += bias[col + 1];
                }
                if (MODE == 3) {
                    d0 = 0.5f*d0*(1.f + erff(d0*0.70710678118654752f));
                    d1 = 0.5f*d1*(1.f + erff(d1*0.70710678118654752f));
                    __nv_bfloat16 h0,h1,l0,l1;
                    split_bf16(d0,h0,l0); split_bf16(d1,h1,l1);
                    __nv_bfloat162 ph; ph.x=h0; ph.y=h1;
                    __nv_bfloat162 pl; pl.x=l0; pl.y=l1;
                    const size_t o = (size_t)row * N + col;
                    *(__nv_bfloat162*)(Ch + o) = ph;
                    *(__nv_bfloat162*)(Cl + o) = pl;
                } else {
                    if (MODE == 1 || MODE == 2) {
                        const float2 rv = *(const float2*)&res[(size_t)row * N + col];
                        d0 += rv.x; d1 += rv.y;
                    }
                    float2 ov; ov.x = d0; ov.y = d1;
                    *(float2*)&Cf[(size_t)row * N + col] = ov;
                }
            }
        }
    }
}

// ---------------------------------------------------------------------------
// Chunkwise retention (fp32 in, bf16-split out). Math identical to R1 (passed).
// ---------------------------------------------------------------------------
#define RQP 65
#define RVP 33
#define RET_SMEM_FLOATS (128*RQP*2 + 64*RVP + 64*RQP + 128*RVP + 192)

__global__ __launch_bounds__(256)
void retention_kernel(const float* __restrict__ q, const float* __restrict__ k,
                      const float* __restrict__ v,
                      __nv_bfloat16* __restrict__ oh, __nv_bfloat16* __restrict__ ol)
{
    extern __shared__ float sm[];
    float* qsT  = sm;
    float* ksT  = qsT + 128*RQP;
    float* vs   = ksT + 128*RQP;
    float* As   = vs  + 64*RVP;
    float* Ss   = As  + 64*RQP;
    float* powt = Ss  + 128*RVP;
    float* dqs  = powt + 64;
    float* dks  = dqs + 64;

    const int tid = threadIdx.x;
    const int blk = blockIdx.x;
    const int jt  = blk & 7;
    const int h   = (blk >> 3) & 7;
    const int b   = blk >> 6;

    const float bh   = 1.f - exp2f(-5.f - (float)h);
    const float logb = logf(bh);
    const float dc   = expf(logb * (float)CHK);

    if (tid < 64) {
        powt[tid] = expf(logb * (float)tid);
        dqs[tid]  = expf(logb * (float)(tid + 1));
        dks[tid]  = expf(logb * (float)(CHK - 1 - tid));
    }
    for (int i = tid; i < 128*RVP; i += 256) Ss[i] = 0.f;
    __syncthreads();

    const float qscale = 0.08838834764831845f;
    const size_t qbase = (size_t)b * LL * DD     + (size_t)h * DKH;
    const size_t vbase = (size_t)b * LL * (2*DD) + (size_t)h * DVH + (size_t)jt * 32;

    const int ty16 = tid >> 4, tx16 = tid & 15;
    const int warp = tid >> 5, lane = tid & 31;

    for (int n = 0; n < NCHK; n++) {
        #pragma unroll
        for (int l = 0; l < 8; l++) {
            const int lin = tid + l * 256;
            const int t  = lin >> 5;
            const int d  = (lin & 31) * 4;
            const size_t ro = qbase + (size_t)(n*CHK + t) * DD + d;
            const float4 qv = *(const float4*)&q[ro];
            qsT[(d+0)*RQP + t] = qv.x * qscale;
            qsT[(d+1)*RQP + t] = qv.y * qscale;
            qsT[(d+2)*RQP + t] = qv.z * qscale;
            qsT[(d+3)*RQP + t] = qv.w * qscale;
            const float4 kv = *(const float4*)&k[ro];
            ksT[(d+0)*RQP + t] = kv.x;
            ksT[(d+1)*RQP + t] = kv.y;
            ksT[(d+2)*RQP + t] = kv.z;
            ksT[(d+3)*RQP + t] = kv.w;
        }
        #pragma unroll
        for (int l = 0; l < 2; l++) {
            const int lin = tid + l * 256;
            const int s  = lin >> 3;
            const int j  = (lin & 7) * 4;
            const float4 vv = *(const float4*)&v[vbase + (size_t)(n*CHK + s) * (2*DD) + j];
            vs[s*RVP + j+0] = vv.x;
            vs[s*RVP + j+1] = vv.y;
            vs[s*RVP + j+2] = vv.z;
            vs[s*RVP + j+3] = vv.w;
        }
        __syncthreads();

        float areg[4][4];
        #pragma unroll
        for (int i = 0; i < 4; i++)
            #pragma unroll
            for (int j = 0; j < 4; j++) areg[i][j] = 0.f;
        #pragma unroll 4
        for (int d = 0; d < 128; d++) {
            float qv[4], kv[4];
            #pragma unroll
            for (int i = 0; i < 4; i++) qv[i] = qsT[d*RQP + 4*ty16 + i];
            #pragma unroll
            for (int j = 0; j < 4; j++) kv[j] = ksT[d*RQP + 4*tx16 + j];
            #pragma unroll
            for (int i = 0; i < 4; i++)
                #pragma unroll
                for (int j = 0; j < 4; j++)
                    areg[i][j] = fmaf(qv[i], kv[j], areg[i][j]);
        }
        #pragma unroll
        for (int i = 0; i < 4; i++) {
            const int t = 4*ty16 + i;
            #pragma unroll
            for (int j = 0; j < 4; j++) {
                const int s = 4*tx16 + j;
                As[t*RQP + s] = (t >= s) ? areg[i][j] * powt[t - s] : 0.f;
            }
        }
        __syncthreads();

        float acc1[8], acc2[8];
        #pragma unroll
        for (int r = 0; r < 8; r++) { acc1[r] = 0.f; acc2[r] = 0.f; }
        const int t0 = warp * 8;
        #pragma unroll 4
        for (int s = 0; s < 64; s++) {
            const float vv = vs[s*RVP + lane];
            #pragma unroll
            for (int r = 0; r < 8; r++)
                acc1[r] = fmaf(As[(t0+r)*RQP + s], vv, acc1[r]);
        }
        #pragma unroll 2
        for (int d = 0; d < 128; d++) {
            const float sv = Ss[d*RVP + lane];
            #pragma unroll
            for (int r = 0; r < 8; r++)
                acc2[r] = fmaf(qsT[d*RQP + t0 + r], sv, acc2[r]);
        }
        #pragma unroll
        for (int r = 0; r < 8; r++) {
            const int t = t0 + r;
            const float val = acc1[r] + dqs[t] * acc2[r];
            const size_t idx = vbase + (size_t)(n*CHK + t) * (2*DD) + lane;
            __nv_bfloat16 hv, lv; split_bf16(val, hv, lv);
            oh[idx] = hv; ol[idx] = lv;
        }
        __syncthreads();

        float sacc[16];
        #pragma unroll
        for (int dd = 0; dd < 16; dd++) sacc[dd] = 0.f;
        const int d0 = warp * 16;
        #pragma unroll 2
        for (int s = 0; s < 64; s++) {
            const float vv = vs[s*RVP + lane] * dks[s];
            #pragma unroll
            for (int dd = 0; dd < 16; dd++)
                sacc[dd] = fmaf(ksT[(d0+dd)*RQP + s], vv, sacc[dd]);
        }
        #pragma unroll
        for (int dd = 0; dd < 16; dd++) {
            const int idx = (d0+dd)*RVP + lane;
            Ss[idx] = Ss[idx] * dc + sacc[dd];
        }
        __syncthreads();
    }
}

// ---------------------------------------------------------------------------
// launch
// ---------------------------------------------------------------------------
extern "C" void kernel_launch(void* const* d_in, const int* in_sizes, int n_in,
                              void* d_out, int out_size)
{
    const float* x     = (const float*)d_in[0];
    const float* ln1_w = (const float*)d_in[1];
    const float* ln1_b = (const float*)d_in[2];
    const float* Wq    = (const float*)d_in[3];
    const float* Wk    = (const float*)d_in[4];
    const float* Wv    = (const float*)d_in[5];
    const float* Wo    = (const float*)d_in[6];
    const float* ln2_w = (const float*)d_in[7];
    const float* ln2_b = (const float*)d_in[8];
    const float* W1    = (const float*)d_in[9];
    const float* b1    = (const float*)d_in[10];
    const float* W2    = (const float*)d_in[11];
    const float* b2    = (const float*)d_in[12];
    float* out = (float*)d_out;

    float *q, *k, *v, *x1;
    __nv_bfloat16 *hh,*hl,*oh,*ol,*fh,*fl,*gh,*gl;
    __nv_bfloat16 *wqh,*wql,*wkh,*wkl,*wvh,*wvl,*woh,*wol,*w1h,*w1l,*w2h,*w2l;
    cudaGetSymbolAddress((void**)&q,  g_q);
    cudaGetSymbolAddress((void**)&k,  g_k);
    cudaGetSymbolAddress((void**)&v,  g_v);
    cudaGetSymbolAddress((void**)&x1, g_x1);
    cudaGetSymbolAddress((void**)&hh, g_hh); cudaGetSymbolAddress((void**)&hl, g_hl);
    cudaGetSymbolAddress((void**)&oh, g_oh); cudaGetSymbolAddress((void**)&ol, g_ol);
    cudaGetSymbolAddress((void**)&fh, g_fh); cudaGetSymbolAddress((void**)&fl, g_fl);
    cudaGetSymbolAddress((void**)&gh, g_gh); cudaGetSymbolAddress((void**)&gl, g_gl);
    cudaGetSymbolAddress((void**)&wqh, g_wqh); cudaGetSymbolAddress((void**)&wql, g_wql);
    cudaGetSymbolAddress((void**)&wkh, g_wkh); cudaGetSymbolAddress((void**)&wkl, g_wkl);
    cudaGetSymbolAddress((void**)&wvh, g_wvh); cudaGetSymbolAddress((void**)&wvl, g_wvl);
    cudaGetSymbolAddress((void**)&woh, g_woh); cudaGetSymbolAddress((void**)&wol, g_wol);
    cudaGetSymbolAddress((void**)&w1h, g_w1h); cudaGetSymbolAddress((void**)&w1l, g_w1l);
    cudaGetSymbolAddress((void**)&w2h, g_w2h); cudaGetSymbolAddress((void**)&w2l, g_w2l);

    cudaFuncSetAttribute(gemm_tc<0>, cudaFuncAttributeMaxDynamicSharedMemorySize, GEMM_SMEM);
    cudaFuncSetAttribute(gemm_tc<1>, cudaFuncAttributeMaxDynamicSharedMemorySize, GEMM_SMEM);
    cudaFuncSetAttribute(gemm_tc<2>, cudaFuncAttributeMaxDynamicSharedMemorySize, GEMM_SMEM);
    cudaFuncSetAttribute(gemm_tc<3>, cudaFuncAttributeMaxDynamicSharedMemorySize, GEMM_SMEM);
    const int ret_smem = RET_SMEM_FLOATS * (int)sizeof(float);
    cudaFuncSetAttribute(retention_kernel,
                         cudaFuncAttributeMaxDynamicSharedMemorySize, ret_smem);

    // weight transpose+split
    wsplit<<<dim3(DD/32,   DD/32),   256>>>(Wq, wqh, wql, DD,   DD);
    wsplit<<<dim3(DD/32,   DD/32),   256>>>(Wk, wkh, wkl, DD,   DD);
    wsplit<<<dim3(2*DD/32, DD/32),   256>>>(Wv, wvh, wvl, DD,   2*DD);
    wsplit<<<dim3(DD/32,   2*DD/32), 256>>>(Wo, woh, wol, 2*DD, DD);
    wsplit<<<dim3(FFND/32, DD/32),   256>>>(W1, w1h, w1l, DD,   FFND);
    wsplit<<<dim3(DD/32,   FFND/32), 256>>>(W2, w2h, w2l, FFND, DD);

    // ln1
    ln_split<<<ROWS, 256>>>(x, ln1_w, ln1_b, hh, hl);

    // q,k,v projections
    gemm_tc<0><<<dim3(DD/GN,   ROWS/GM), 256, GEMM_SMEM>>>(hh, hl, wqh, wql,
        nullptr, nullptr, q, nullptr, nullptr, ROWS, DD, DD);
    gemm_tc<0><<<dim3(DD/GN,   ROWS/GM), 256, GEMM_SMEM>>>(hh, hl, wkh, wkl,
        nullptr, nullptr, k, nullptr, nullptr, ROWS, DD, DD);
    gemm_tc<0><<<dim3(2*DD/GN, ROWS/GM), 256, GEMM_SMEM>>>(hh, hl, wvh, wvl,
        nullptr, nullptr, v, nullptr, nullptr, ROWS, 2*DD, DD);

    // retention
    retention_kernel<<<BB*HH*(DVH/32), 256, ret_smem>>>(q, k, v, oh, ol);

    // x1 = x + o @ Wo
    gemm_tc<1><<<dim3(DD/GN, ROWS/GM), 256, GEMM_SMEM>>>(oh, ol, woh, wol,
        nullptr, x, x1, nullptr, nullptr, ROWS, DD, 2*DD);

    // ln2
    ln_split<<<ROWS, 256>>>(x1, ln2_w, ln2_b, fh, fl);

    // g = gelu(f @ W1 + b1)   (split bf16 out)
    gemm_tc<3><<<dim3(FFND/GN, ROWS/GM), 256, GEMM_SMEM>>>(fh, fl, w1h, w1l,
        b1, nullptr, nullptr, gh, gl, ROWS, FFND, DD);

    // out = x1 + g @ W2 + b2
    gemm_tc<2><<<dim3(DD/GN, ROWS/GM), 256, GEMM_SMEM>>>(gh, gl, w2h, w2l,
        b2, x1, out, nullptr, nullptr, ROWS, DD, FFND);
}

// round 12
// speedup vs baseline: 1.0195x; 1.0195x over previous
#include <cuda_runtime.h>
#include <cuda_bf16.h>
#include <math.h>
#include <stdint.h>

// ---------------------------------------------------------------------------
// Problem constants
// ---------------------------------------------------------------------------
#define BB   2
#define LL   4096
#define DD   1024
#define HH   8
#define DKH  128
#define DVH  256
#define FFND 4096
#define ROWS (BB*LL)          // 8192
#define CHK  64
#define NCHK (LL/CHK)

// ---------------------------------------------------------------------------
// Scratch (device globals -- no allocation allowed)
// ---------------------------------------------------------------------------
__device__ float g_q [ROWS*DD];
__device__ float g_k [ROWS*DD];
__device__ float g_v [ROWS*2*DD];
__device__ float g_x1[ROWS*DD];

__device__ __nv_bfloat16 g_hh[ROWS*DD],   g_hl[ROWS*DD];     // ln1 out split
__device__ __nv_bfloat16 g_oh[ROWS*2*DD], g_ol[ROWS*2*DD];   // retention out split
__device__ __nv_bfloat16 g_fh[ROWS*DD],   g_fl[ROWS*DD];     // ln2 out split
__device__ __nv_bfloat16 g_gh[ROWS*FFND], g_gl[ROWS*FFND];   // gelu out split

// transposed weight splits, [N,K] K-major
__device__ __nv_bfloat16 g_wqh[DD*DD],     g_wql[DD*DD];
__device__ __nv_bfloat16 g_wkh[DD*DD],     g_wkl[DD*DD];
__device__ __nv_bfloat16 g_wvh[2*DD*DD],   g_wvl[2*DD*DD];
__device__ __nv_bfloat16 g_woh[DD*2*DD],   g_wol[DD*2*DD];
__device__ __nv_bfloat16 g_w1h[FFND*DD],   g_w1l[FFND*DD];
__device__ __nv_bfloat16 g_w2h[DD*FFND],   g_w2l[DD*FFND];

// ---------------------------------------------------------------------------
// PTX helpers (baseline PTX only -- no sm_103a-only features)
// ---------------------------------------------------------------------------
__device__ __forceinline__ uint32_t smem_u32(const void* p){
    uint32_t a;
    asm("{ .reg .u64 t; cvta.to.shared.u64 t, %1; cvt.u32.u64 %0, t; }"
        : "=r"(a) : "l"(p));
    return a;
}
__device__ __forceinline__ void cpa16(uint32_t d, const void* s){
    asm volatile("cp.async.cg.shared.global [%0], [%1], 16;" :: "r"(d), "l"(s));
}
#define CP_COMMIT() asm volatile("cp.async.commit_group;" ::: "memory")
#define CP_WAIT0()  asm volatile("cp.async.wait_group 0;" ::: "memory")
#define CP_WAIT1()  asm volatile("cp.async.wait_group 1;" ::: "memory")

__device__ __forceinline__ void ldsm4(uint32_t& r0, uint32_t& r1,
                                      uint32_t& r2, uint32_t& r3, uint32_t a){
    asm volatile("ldmatrix.sync.aligned.m8n8.x4.shared.b16 {%0,%1,%2,%3}, [%4];"
                 : "=r"(r0), "=r"(r1), "=r"(r2), "=r"(r3) : "r"(a));
}
__device__ __forceinline__ void mma16816(float* d, const uint32_t* a, const uint32_t* b){
    asm volatile("mma.sync.aligned.m16n8k16.row.col.f32.bf16.bf16.f32 "
                 "{%0,%1,%2,%3}, {%4,%5,%6,%7}, {%8,%9}, {%0,%1,%2,%3};"
                 : "+f"(d[0]), "+f"(d[1]), "+f"(d[2]), "+f"(d[3])
                 : "r"(a[0]), "r"(a[1]), "r"(a[2]), "r"(a[3]),
                   "r"(b[0]), "r"(b[1]));
}

__device__ __forceinline__ void split_bf16(float v, __nv_bfloat16& h, __nv_bfloat16& l){
    h = __float2bfloat16(v);
    l = __float2bfloat16(v - __bfloat162float(h));
}

// ---------------------------------------------------------------------------
// LayerNorm -> bf16 hi/lo split
// ---------------------------------------------------------------------------
__global__ void ln_split(const float* __restrict__ x,
                         const float* __restrict__ w,
                         const float* __restrict__ b,
                         __nv_bfloat16* __restrict__ yh,
                         __nv_bfloat16* __restrict__ yl)
{
    const int t = threadIdx.x;
    const size_t row = blockIdx.x;
    const float4 v = ((const float4*)(x + row*DD))[t];

    float s  = v.x + v.y + v.z + v.w;
    float ss = v.x*v.x + v.y*v.y + v.z*v.z + v.w*v.w;
    #pragma unroll
    for (int o = 16; o; o >>= 1) {
        s  += __shfl_xor_sync(0xffffffffu, s,  o);
        ss += __shfl_xor_sync(0xffffffffu, ss, o);
    }
    __shared__ float sh[16];
    if ((t & 31) == 0) { sh[t >> 5] = s; sh[8 + (t >> 5)] = ss; }
    __syncthreads();
    float S = 0.f, SS = 0.f;
    #pragma unroll
    for (int i = 0; i < 8; i++) { S += sh[i]; SS += sh[8 + i]; }
    const float mu   = S * (1.f / DD);
    const float rstd = rsqrtf(SS * (1.f / DD) - mu * mu + 1e-6f);

    const float4 wv = ((const float4*)w)[t];
    const float4 bv = ((const float4*)b)[t];
    float o0 = (v.x - mu) * rstd * wv.x + bv.x;
    float o1 = (v.y - mu) * rstd * wv.y + bv.y;
    float o2 = (v.z - mu) * rstd * wv.z + bv.z;
    float o3 = (v.w - mu) * rstd * wv.w + bv.w;

    __nv_bfloat16 h0,h1,h2,h3,l0,l1,l2,l3;
    split_bf16(o0,h0,l0); split_bf16(o1,h1,l1);
    split_bf16(o2,h2,l2); split_bf16(o3,h3,l3);
    const size_t base = row*DD + 4*t;
    __nv_bfloat162 ph0; ph0.x=h0; ph0.y=h1;
    __nv_bfloat162 ph1; ph1.x=h2; ph1.y=h3;
    __nv_bfloat162 pl0; pl0.x=l0; pl0.y=l1;
    __nv_bfloat162 pl1; pl1.x=l2; pl1.y=l3;
    ((__nv_bfloat162*)(yh+base))[0] = ph0;
    ((__nv_bfloat162*)(yh+base))[1] = ph1;
    ((__nv_bfloat162*)(yl+base))[0] = pl0;
    ((__nv_bfloat162*)(yl+base))[1] = pl1;
}

// ---------------------------------------------------------------------------
// Weight transpose + split: W[K,N] fp32 -> Wh/Wl [N,K] bf16
// ---------------------------------------------------------------------------
__global__ void wsplit(const float* __restrict__ W,
                       __nv_bfloat16* __restrict__ Wh,
                       __nv_bfloat16* __restrict__ Wl, int K, int N)
{
    __shared__ float t[32][33];
    const int n0 = blockIdx.x*32, k0 = blockIdx.y*32;
    const int tx = threadIdx.x & 31, ty = threadIdx.x >> 5;   // ty 0..7
    #pragma unroll
    for (int i = 0; i < 32; i += 8)
        t[ty+i][tx] = W[(size_t)(k0+ty+i)*N + n0+tx];
    __syncthreads();
    #pragma unroll
    for (int i = 0; i < 32; i += 8) {
        const float v = t[tx][ty+i];
        __nv_bfloat16 h,l; split_bf16(v,h,l);
        const size_t o = (size_t)(n0+ty+i)*K + k0+tx;
        Wh[o] = h; Wl[o] = l;
    }
}

// ---------------------------------------------------------------------------
// mma.sync bf16 split-GEMM: C = (Ah+Al)[M,K] @ (Bh+Bl)[N,K]^T  (3 products)
// CTA 128x128, BK=32, 3-stage cp.async, 8 warps (2x4), warp tile 64x32.
// SMEM rows padded to 80B -> ldmatrix conflict-free (20r mod 32 covers all
// eight 4-bank groups).
// MODE 0: Cf = acc
// MODE 1: Cf = acc + res
// MODE 2: Cf = acc + bias + res
// MODE 3: Ch/Cl = split(gelu(acc + bias))
// ---------------------------------------------------------------------------
#define GM 128
#define GN 128
#define GK 32
#define NST 3
#define ROWB 80                    // 32 bf16 data + 16B pad
#define MATB (128*ROWB)            // 10240 B per matrix per stage
#define STGB (4*MATB)              // Ah,Al,Bh,Bl = 40960 B
#define GEMM_SMEM (NST*STGB)       // 122880 B

template<int MODE>
__global__ __launch_bounds__(256)
void gemm_tc(const __nv_bfloat16* __restrict__ Ah, const __nv_bfloat16* __restrict__ Al,
             const __nv_bfloat16* __restrict__ Bh, const __nv_bfloat16* __restrict__ Bl,
             const float* __restrict__ bias, const float* __restrict__ res,
             float* __restrict__ Cf,
             __nv_bfloat16* __restrict__ Ch, __nv_bfloat16* __restrict__ Cl,
             int M, int N, int K)
{
    extern __shared__ char smc[];
    const uint32_t sb = smem_u32(smc);
    const int tid  = threadIdx.x;
    const int wid  = tid >> 5, lane = tid & 31;
    const int m0 = blockIdx.y * GM, n0 = blockIdx.x * GN;

    const int NIT = K / GK;

    // cp.async fill of one stage: 2048 16B chunks, 8 per thread
    auto fill = [&](int kt){
        const int kb = kt * GK;
        const uint32_t tb = sb + (kt % NST) * STGB;
        #pragma unroll
        for (int i = 0; i < 8; i++) {
            const int g   = tid + i * 256;      // 0..2047
            const int m   = g >> 9;             // 0..3 : Ah,Al,Bh,Bl
            const int c   = g & 511;
            const int row = c >> 2;
            const int cb  = (c & 3) * 16;       // byte offset in k dim
            const uint32_t dst = tb + m * MATB + row * ROWB + cb;
            const int ke = kb + (cb >> 1);
            const __nv_bfloat16* sp;
            if      (m == 0) sp = Ah + (size_t)(m0 + row) * K + ke;
            else if (m == 1) sp = Al + (size_t)(m0 + row) * K + ke;
            else if (m == 2) sp = Bh + (size_t)(n0 + row) * K + ke;
            else             sp = Bl + (size_t)(n0 + row) * K + ke;
            cpa16(dst, sp);
        }
        CP_COMMIT();
    };

    fill(0);
    fill(1);

    // warp tiling
    const int wr = (wid & 1) * 64;              // warp M origin
    const int wc = (wid >> 1) * 32;             // warp N origin
    // ldmatrix per-lane row offsets (bytes, within a matrix)
    const uint32_t alr = (uint32_t)(wr + (lane & 15)) * ROWB + (uint32_t)(lane >> 4) * 16;
    const uint32_t bnr = (uint32_t)(wc + (lane & 7) + ((lane >> 4) << 3)) * ROWB
                       + (uint32_t)((lane >> 3) & 1) * 16;

    float acc[4][4][4];
    #pragma unroll
    for (int i = 0; i < 4; i++)
        #pragma unroll
        for (int j = 0; j < 4; j++)
            #pragma unroll
            for (int e = 0; e < 4; e++) acc[i][j][e] = 0.f;

    for (int kt = 0; kt < NIT; kt++) {
        if (kt == NIT - 1) CP_WAIT0(); else CP_WAIT1();
        __syncthreads();
        if (kt + 2 < NIT) fill(kt + 2);

        const uint32_t sA_h = sb + (kt % NST) * STGB;
        const uint32_t sA_l = sA_h + MATB;
        const uint32_t sB_h = sA_h + 2*MATB;
        const uint32_t sB_l = sA_h + 3*MATB;

        #pragma unroll
        for (int kk2 = 0; kk2 < 2; kk2++) {
            const uint32_t ko = kk2 * 32;       // 16 bf16 = 32 bytes
            uint32_t ah[4][4], al[4][4], bh[4][2], bl[4][2];
            #pragma unroll
            for (int mi = 0; mi < 4; mi++) {
                ldsm4(ah[mi][0], ah[mi][1], ah[mi][2], ah[mi][3],
                      sA_h + alr + mi*16*ROWB + ko);
                ldsm4(al[mi][0], al[mi][1], al[mi][2], al[mi][3],
                      sA_l + alr + mi*16*ROWB + ko);
            }
            #pragma unroll
            for (int nj2 = 0; nj2 < 2; nj2++) {
                uint32_t r0,r1,r2,r3;
                ldsm4(r0,r1,r2,r3, sB_h + bnr + nj2*16*ROWB + ko);
                bh[2*nj2][0]=r0; bh[2*nj2][1]=r1; bh[2*nj2+1][0]=r2; bh[2*nj2+1][1]=r3;
                ldsm4(r0,r1,r2,r3, sB_l + bnr + nj2*16*ROWB + ko);
                bl[2*nj2][0]=r0; bl[2*nj2][1]=r1; bl[2*nj2+1][0]=r2; bl[2*nj2+1][1]=r3;
            }
            #pragma unroll
            for (int mi = 0; mi < 4; mi++)
                #pragma unroll
                for (int nj = 0; nj < 4; nj++) {
                    mma16816(acc[mi][nj], ah[mi], bh[nj]);
                    mma16816(acc[mi][nj], ah[mi], bl[nj]);
                    mma16816(acc[mi][nj], al[mi], bh[nj]);
                }
        }
        __syncthreads();
    }

    // ------------------- epilogue -------------------
    const int cr = lane >> 2;          // 0..7
    const int cc = (lane & 3) * 2;     // 0,2,4,6
    #pragma unroll
    for (int mi = 0; mi < 4; mi++) {
        #pragma unroll
        for (int half = 0; half < 2; half++) {
            const int row = m0 + wr + 16*mi + cr + 8*half;
            #pragma unroll
            for (int nj = 0; nj < 4; nj++) {
                float d0 = acc[mi][nj][2*half + 0];
                float d1 = acc[mi][nj][2*half + 1];
                const int col = n0 + wc + 8*nj + cc;
                if (MODE == 2 || MODE == 3) {
                    d0 += bias[col]; d1 += bias[col + 1];
                }
                if (MODE == 3) {
                    d0 = 0.5f*d0*(1.f + erff(d0*0.70710678118654752f));
                    d1 = 0.5f*d1*(1.f + erff(d1*0.70710678118654752f));
                    __nv_bfloat16 h0,h1,l0,l1;
                    split_bf16(d0,h0,l0); split_bf16(d1,h1,l1);
                    __nv_bfloat162 ph; ph.x=h0; ph.y=h1;
                    __nv_bfloat162 pl; pl.x=l0; pl.y=l1;
                    const size_t o = (size_t)row * N + col;
                    *(__nv_bfloat162*)(Ch + o) = ph;
                    *(__nv_bfloat162*)(Cl + o) = pl;
                } else {
                    if (MODE == 1 || MODE == 2) {
                        const float2 rv = *(const float2*)&res[(size_t)row * N + col];
                        d0 += rv.x; d1 += rv.y;
                    }
                    float2 ov; ov.x = d0; ov.y = d1;
                    *(float2*)&Cf[(size_t)row * N + col] = ov;
                }
            }
        }
    }
}

// ---------------------------------------------------------------------------
// Chunkwise retention (fp32 in, bf16-split out). Math identical to R1 (passed).
// ---------------------------------------------------------------------------
#define RQP 65
#define RVP 33
#define RET_SMEM_FLOATS (128*RQP*2 + 64*RVP + 64*RQP + 128*RVP + 192)

__global__ __launch_bounds__(256)
void retention_kernel(const float* __restrict__ q, const float* __restrict__ k,
                      const float* __restrict__ v,
                      __nv_bfloat16* __restrict__ oh, __nv_bfloat16* __restrict__ ol)
{
    extern __shared__ float sm[];
    float* qsT  = sm;
    float* ksT  = qsT + 128*RQP;
    float* vs   = ksT + 128*RQP;
    float* As   = vs  + 64*RVP;
    float* Ss   = As  + 64*RQP;
    float* powt = Ss  + 128*RVP;
    float* dqs  = powt + 64;
    float* dks  = dqs + 64;

    const int tid = threadIdx.x;
    const int blk = blockIdx.x;
    const int jt  = blk & 7;
    const int h   = (blk >> 3) & 7;
    const int b   = blk >> 6;

    const float bh   = 1.f - exp2f(-5.f - (float)h);
    const float logb = logf(bh);
    const float dc   = expf(logb * (float)CHK);

    if (tid < 64) {
        powt[tid] = expf(logb * (float)tid);
        dqs[tid]  = expf(logb * (float)(tid + 1));
        dks[tid]  = expf(logb * (float)(CHK - 1 - tid));
    }
    for (int i = tid; i < 128*RVP; i += 256) Ss[i] = 0.f;
    __syncthreads();

    const float qscale = 0.08838834764831845f;
    const size_t qbase = (size_t)b * LL * DD     + (size_t)h * DKH;
    const size_t vbase = (size_t)b * LL * (2*DD) + (size_t)h * DVH + (size_t)jt * 32;

    const int ty16 = tid >> 4, tx16 = tid & 15;
    const int warp = tid >> 5, lane = tid & 31;

    for (int n = 0; n < NCHK; n++) {
        #pragma unroll
        for (int l = 0; l < 8; l++) {
            const int lin = tid + l * 256;
            const int t  = lin >> 5;
            const int d  = (lin & 31) * 4;
            const size_t ro = qbase + (size_t)(n*CHK + t) * DD + d;
            const float4 qv = *(const float4*)&q[ro];
            qsT[(d+0)*RQP + t] = qv.x * qscale;
            qsT[(d+1)*RQP + t] = qv.y * qscale;
            qsT[(d+2)*RQP + t] = qv.z * qscale;
            qsT[(d+3)*RQP + t] = qv.w * qscale;
            const float4 kv = *(const float4*)&k[ro];
            ksT[(d+0)*RQP + t] = kv.x;
            ksT[(d+1)*RQP + t] = kv.y;
            ksT[(d+2)*RQP + t] = kv.z;
            ksT[(d+3)*RQP + t] = kv.w;
        }
        #pragma unroll
        for (int l = 0; l < 2; l++) {
            const int lin = tid + l * 256;
            const int s  = lin >> 3;
            const int j  = (lin & 7) * 4;
            const float4 vv = *(const float4*)&v[vbase + (size_t)(n*CHK + s) * (2*DD) + j];
            vs[s*RVP + j+0] = vv.x;
            vs[s*RVP + j+1] = vv.y;
            vs[s*RVP + j+2] = vv.z;
            vs[s*RVP + j+3] = vv.w;
        }
        __syncthreads();

        float areg[4][4];
        #pragma unroll
        for (int i = 0; i < 4; i++)
            #pragma unroll
            for (int j = 0; j < 4; j++) areg[i][j] = 0.f;
        #pragma unroll 4
        for (int d = 0; d < 128; d++) {
            float qv[4], kv[4];
            #pragma unroll
            for (int i = 0; i < 4; i++) qv[i] = qsT[d*RQP + 4*ty16 + i];
            #pragma unroll
            for (int j = 0; j < 4; j++) kv[j] = ksT[d*RQP + 4*tx16 + j];
            #pragma unroll
            for (int i = 0; i < 4; i++)
                #pragma unroll
                for (int j = 0; j < 4; j++)
                    areg[i][j] = fmaf(qv[i], kv[j], areg[i][j]);
        }
        #pragma unroll
        for (int i = 0; i < 4; i++) {
            const int t = 4*ty16 + i;
            #pragma unroll
            for (int j = 0; j < 4; j++) {
                const int s = 4*tx16 + j;
                As[t*RQP + s] = (t >= s) ? areg[i][j] * powt[t - s] : 0.f;
            }
        }
        __syncthreads();

        float acc1[8], acc2[8];
        #pragma unroll
        for (int r = 0; r < 8; r++) { acc1[r] = 0.f; acc2[r] = 0.f; }
        const int t0 = warp * 8;
        #pragma unroll 4
        for (int s = 0; s < 64; s++) {
            const float vv = vs[s*RVP + lane];
            #pragma unroll
            for (int r = 0; r < 8; r++)
                acc1[r] = fmaf(As[(t0+r)*RQP + s], vv, acc1[r]);
        }
        #pragma unroll 2
        for (int d = 0; d < 128; d++) {
            const float sv = Ss[d*RVP + lane];
            #pragma unroll
            for (int r = 0; r < 8; r++)
                acc2[r] = fmaf(qsT[d*RQP + t0 + r], sv, acc2[r]);
        }
        #pragma unroll
        for (int r = 0; r < 8; r++) {
            const int t = t0 + r;
            const float val = acc1[r] + dqs[t] * acc2[r];
            const size_t idx = vbase + (size_t)(n*CHK + t) * (2*DD) + lane;
            __nv_bfloat16 hv, lv; split_bf16(val, hv, lv);
            oh[idx] = hv; ol[idx] = lv;
        }
        __syncthreads();

        float sacc[16];
        #pragma unroll
        for (int dd = 0; dd < 16; dd++) sacc[dd] = 0.f;
        const int d0 = warp * 16;
        #pragma unroll 2
        for (int s = 0; s < 64; s++) {
            const float vv = vs[s*RVP + lane] * dks[s];
            #pragma unroll
            for (int dd = 0; dd < 16; dd++)
                sacc[dd] = fmaf(ksT[(d0+dd)*RQP + s], vv, sacc[dd]);
        }
        #pragma unroll
        for (int dd = 0; dd < 16; dd++) {
            const int idx = (d0+dd)*RVP + lane;
            Ss[idx] = Ss[idx] * dc + sacc[dd];
        }
        __syncthreads();
    }
}

// ---------------------------------------------------------------------------
// launch
// ---------------------------------------------------------------------------
extern "C" void kernel_launch(void* const* d_in, const int* in_sizes, int n_in,
                              void* d_out, int out_size)
{
    const float* x     = (const float*)d_in[0];
    const float* ln1_w = (const float*)d_in[1];
    const float* ln1_b = (const float*)d_in[2];
    const float* Wq    = (const float*)d_in[3];
    const float* Wk    = (const float*)d_in[4];
    const float* Wv    = (const float*)d_in[5];
    const float* Wo    = (const float*)d_in[6];
    const float* ln2_w = (const float*)d_in[7];
    const float* ln2_b = (const float*)d_in[8];
    const float* W1    = (const float*)d_in[9];
    const float* b1    = (const float*)d_in[10];
    const float* W2    = (const float*)d_in[11];
    const float* b2    = (const float*)d_in[12];
    float* out = (float*)d_out;

    float *q, *k, *v, *x1;
    __nv_bfloat16 *hh,*hl,*oh,*ol,*fh,*fl,*gh,*gl;
    __nv_bfloat16 *wqh,*wql,*wkh,*wkl,*wvh,*wvl,*woh,*wol,*w1h,*w1l,*w2h,*w2l;
    cudaGetSymbolAddress((void**)&q,  g_q);
    cudaGetSymbolAddress((void**)&k,  g_k);
    cudaGetSymbolAddress((void**)&v,  g_v);
    cudaGetSymbolAddress((void**)&x1, g_x1);
    cudaGetSymbolAddress((void**)&hh, g_hh); cudaGetSymbolAddress((void**)&hl, g_hl);
    cudaGetSymbolAddress((void**)&oh, g_oh); cudaGetSymbolAddress((void**)&ol, g_ol);
    cudaGetSymbolAddress((void**)&fh, g_fh); cudaGetSymbolAddress((void**)&fl, g_fl);
    cudaGetSymbolAddress((void**)&gh, g_gh); cudaGetSymbolAddress((void**)&gl, g_gl);
    cudaGetSymbolAddress((void**)&wqh, g_wqh); cudaGetSymbolAddress((void**)&wql, g_wql);
    cudaGetSymbolAddress((void**)&wkh, g_wkh); cudaGetSymbolAddress((void**)&wkl, g_wkl);
    cudaGetSymbolAddress((void**)&wvh, g_wvh); cudaGetSymbolAddress((void**)&wvl, g_wvl);
    cudaGetSymbolAddress((void**)&woh, g_woh); cudaGetSymbolAddress((void**)&wol, g_wol);
    cudaGetSymbolAddress((void**)&w1h, g_w1h); cudaGetSymbolAddress((void**)&w1l, g_w1l);
    cudaGetSymbolAddress((void**)&w2h, g_w2h); cudaGetSymbolAddress((void**)&w2l, g_w2l);

    cudaFuncSetAttribute(gemm_tc<0>, cudaFuncAttributeMaxDynamicSharedMemorySize, GEMM_SMEM);
    cudaFuncSetAttribute(gemm_tc<1>, cudaFuncAttributeMaxDynamicSharedMemorySize, GEMM_SMEM);
    cudaFuncSetAttribute(gemm_tc<2>, cudaFuncAttributeMaxDynamicSharedMemorySize, GEMM_SMEM);
    cudaFuncSetAttribute(gemm_tc<3>, cudaFuncAttributeMaxDynamicSharedMemorySize, GEMM_SMEM);
    const int ret_smem = RET_SMEM_FLOATS * (int)sizeof(float);
    cudaFuncSetAttribute(retention_kernel,
                         cudaFuncAttributeMaxDynamicSharedMemorySize, ret_smem);

    // weight transpose+split
    wsplit<<<dim3(DD/32,   DD/32),   256>>>(Wq, wqh, wql, DD,   DD);
    wsplit<<<dim3(DD/32,   DD/32),   256>>>(Wk, wkh, wkl, DD,   DD);
    wsplit<<<dim3(2*DD/32, DD/32),   256>>>(Wv, wvh, wvl, DD,   2*DD);
    wsplit<<<dim3(DD/32,   2*DD/32), 256>>>(Wo, woh, wol, 2*DD, DD);
    wsplit<<<dim3(FFND/32, DD/32),   256>>>(W1, w1h, w1l, DD,   FFND);
    wsplit<<<dim3(DD/32,   FFND/32), 256>>>(W2, w2h, w2l, FFND, DD);

    // ln1
    ln_split<<<ROWS, 256>>>(x, ln1_w, ln1_b, hh, hl);

    // q,k,v projections
    gemm_tc<0><<<dim3(DD/GN,   ROWS/GM), 256, GEMM_SMEM>>>(hh, hl, wqh, wql,
        nullptr, nullptr, q, nullptr, nullptr, ROWS, DD, DD);
    gemm_tc<0><<<dim3(DD/GN,   ROWS/GM), 256, GEMM_SMEM>>>(hh, hl, wkh, wkl,
        nullptr, nullptr, k, nullptr, nullptr, ROWS, DD, DD);
    gemm_tc<0><<<dim3(2*DD/GN, ROWS/GM), 256, GEMM_SMEM>>>(hh, hl, wvh, wvl,
        nullptr, nullptr, v, nullptr, nullptr, ROWS, 2*DD, DD);

    // retention
    retention_kernel<<<BB*HH*(DVH/32), 256, ret_smem>>>(q, k, v, oh, ol);

    // x1 = x + o @ Wo
    gemm_tc<1><<<dim3(DD/GN, ROWS/GM), 256, GEMM_SMEM>>>(oh, ol, woh, wol,
        nullptr, x, x1, nullptr, nullptr, ROWS, DD, 2*DD);

    // ln2
    ln_split<<<ROWS, 256>>>(x1, ln2_w, ln2_b, fh, fl);

    // g = gelu(f @ W1 + b1)   (split bf16 out)
    gemm_tc<3><<<dim3(FFND/GN, ROWS/GM), 256, GEMM_SMEM>>>(fh, fl, w1h, w1l,
        b1, nullptr, nullptr, gh, gl, ROWS, FFND, DD);

    // out = x1 + g @ W2 + b2
    gemm_tc<2><<<dim3(DD/GN, ROWS/GM), 256, GEMM_SMEM>>>(gh, gl, w2h, w2l,
        b2, x1, out, nullptr, nullptr, ROWS, DD, FFND);
}